// round 10
// baseline (speedup 1.0000x reference)
#include <cuda_runtime.h>
#include <cstdint>
#include <math.h>

#define DIM       1024
#define NHEADS    16
#define HDIM      64
#define BATCH     4
#define SEQ       8192
#define LAT       512
#define SCALE     0.125f   // 64^-0.5

#if defined(__CUDA_ARCH_FEAT_SM103_ALL) || defined(__CUDA_ARCH_FEAT_SM100_ALL) || \
    (defined(__CUDA_ARCH_SPECIFIC__) && (__CUDA_ARCH_SPECIFIC__ >= 1000))
#define HAS_TCGEN05 1
#else
#define HAS_TCGEN05 0
#endif

// -------- scratch (device globals; no allocation allowed) --------
__device__ float g_q  [(size_t)BATCH * LAT * DIM];                    // 8 MB
__device__ float g_kv [(size_t)BATCH * SEQ * 2 * DIM];                // 268 MB
__device__ float g_att[(size_t)BATCH * LAT * DIM];                    // 8 MB
__device__ float g_vt [(size_t)BATCH * NHEADS * HDIM * SEQ];          // 134 MB (V^T, tf32)

// ================= helpers =================
__device__ __forceinline__ uint32_t smem_u32(const void* p) {
    uint32_t a;
    asm("{ .reg .u64 t; cvta.to.shared.u64 t, %1; cvt.u32.u64 %0, t; }"
        : "=r"(a) : "l"(p));
    return a;
}
__device__ __forceinline__ uint32_t f2tf32(float f) {
    uint32_t r;
    asm("cvt.rna.tf32.f32 %0, %1;" : "=r"(r) : "f"(f));
    return r;
}

#if HAS_TCGEN05
__device__ __forceinline__ uint32_t elect_one() {
    uint32_t p;
    asm volatile("{ .reg .pred p; elect.sync _|p, 0xFFFFFFFF; selp.b32 %0,1,0,p; }"
                 : "=r"(p));
    return p;
}

#define MBARRIER_INIT(addr, cnt) \
    asm volatile("mbarrier.init.shared.b64 [%0], %1;" :: "r"(addr), "r"(cnt) : "memory")

#define MBARRIER_WAIT_PARITY(mbar, par) do {                                   \
    uint32_t _m = (mbar); uint32_t _p = (par); uint32_t _done;                 \
    asm volatile("{\n\t.reg .pred p;\n\t"                                      \
        "mbarrier.try_wait.parity.acquire.cta.shared::cta.b64 p, [%1], %2;\n\t"\
        "selp.b32 %0, 1, 0, p;\n\t}"                                           \
        : "=r"(_done) : "r"(_m), "r"(_p) : "memory");                          \
    if (!_done) {                                                              \
        asm volatile("{\n\t.reg .pred P1;\n\t"                                 \
            "WL_%=:\n\t"                                                       \
            "mbarrier.try_wait.parity.acquire.cta.shared::cta.b64 P1, [%0], %1, 0x989680;\n\t" \
            "@P1 bra.uni WD_%=;\n\t"                                           \
            "bra.uni WL_%=;\n\t"                                               \
            "WD_%=:\n\t}"                                                      \
            :: "r"(_m), "r"(_p) : "memory");                                   \
    }                                                                          \
} while (0)

#define TCGEN05_ALLOC(slot, n) \
    asm volatile("tcgen05.alloc.cta_group::1.sync.aligned.shared::cta.b32 [%0], %1;" \
                 :: "r"(slot), "r"(n) : "memory")
#define TCGEN05_DEALLOC(tm, n) \
    asm volatile("tcgen05.dealloc.cta_group::1.sync.aligned.b32 %0, %1;" :: "r"(tm), "r"(n))
#define TCGEN05_RELINQ() \
    asm volatile("tcgen05.relinquish_alloc_permit.cta_group::1.sync.aligned;")
#define TCGEN05_COMMIT(mbar) \
    asm volatile("tcgen05.commit.cta_group::1.mbarrier::arrive::one.shared::cluster.b64 [%0];" \
                 :: "r"(mbar) : "memory")
#define TCGEN05_WAIT_LD() asm volatile("tcgen05.wait::ld.sync.aligned;" ::: "memory")
#define TCGEN05_WAIT_ST() asm volatile("tcgen05.wait::st.sync.aligned;" ::: "memory")
#define TCGEN05_FENCE_AFTER() asm volatile("tcgen05.fence::after_thread_sync;" ::: "memory")
#define TCGEN05_FENCE_BEFORE() asm volatile("tcgen05.fence::before_thread_sync;" ::: "memory")
#define FENCE_ASYNC() asm volatile("fence.proxy.async.shared::cta;" ::: "memory")

#define TCGEN05_LD_X32(r, addr)                                                \
    asm volatile("tcgen05.ld.sync.aligned.32x32b.x32.b32 "                     \
        "{%0,%1,%2,%3,%4,%5,%6,%7,%8,%9,%10,%11,%12,%13,%14,%15,"              \
        "%16,%17,%18,%19,%20,%21,%22,%23,%24,%25,%26,%27,%28,%29,%30,%31}, [%32];" \
        : "=r"((r)[0]),"=r"((r)[1]),"=r"((r)[2]),"=r"((r)[3]),                 \
          "=r"((r)[4]),"=r"((r)[5]),"=r"((r)[6]),"=r"((r)[7]),                 \
          "=r"((r)[8]),"=r"((r)[9]),"=r"((r)[10]),"=r"((r)[11]),               \
          "=r"((r)[12]),"=r"((r)[13]),"=r"((r)[14]),"=r"((r)[15]),             \
          "=r"((r)[16]),"=r"((r)[17]),"=r"((r)[18]),"=r"((r)[19]),             \
          "=r"((r)[20]),"=r"((r)[21]),"=r"((r)[22]),"=r"((r)[23]),             \
          "=r"((r)[24]),"=r"((r)[25]),"=r"((r)[26]),"=r"((r)[27]),             \
          "=r"((r)[28]),"=r"((r)[29]),"=r"((r)[30]),"=r"((r)[31])              \
        : "r"(addr))

#define TCGEN05_ST_X32(addr, r)                                                \
    asm volatile("tcgen05.st.sync.aligned.32x32b.x32.b32 [%0], "               \
        "{%1,%2,%3,%4,%5,%6,%7,%8,%9,%10,%11,%12,%13,%14,%15,%16,"             \
        "%17,%18,%19,%20,%21,%22,%23,%24,%25,%26,%27,%28,%29,%30,%31,%32};"    \
        :: "r"(addr),                                                          \
           "r"((r)[0]),"r"((r)[1]),"r"((r)[2]),"r"((r)[3]),                    \
           "r"((r)[4]),"r"((r)[5]),"r"((r)[6]),"r"((r)[7]),                    \
           "r"((r)[8]),"r"((r)[9]),"r"((r)[10]),"r"((r)[11]),                  \
           "r"((r)[12]),"r"((r)[13]),"r"((r)[14]),"r"((r)[15]),                \
           "r"((r)[16]),"r"((r)[17]),"r"((r)[18]),"r"((r)[19]),                \
           "r"((r)[20]),"r"((r)[21]),"r"((r)[22]),"r"((r)[23]),                \
           "r"((r)[24]),"r"((r)[25]),"r"((r)[26]),"r"((r)[27]),                \
           "r"((r)[28]),"r"((r)[29]),"r"((r)[30]),"r"((r)[31])                 \
        : "memory")

__device__ __forceinline__ void mma_tf32_ss(uint32_t d_tmem, uint64_t a_desc,
                                            uint64_t b_desc, uint32_t idesc,
                                            uint32_t enable) {
    asm volatile(
        "{\n\t.reg .pred p;\n\t"
        "setp.ne.u32 p, %4, 0;\n\t"
        "tcgen05.mma.cta_group::1.kind::tf32 [%0], %1, %2, %3, {%5,%5,%5,%5}, p;\n\t}"
        :: "r"(d_tmem), "l"(a_desc), "l"(b_desc), "r"(idesc), "r"(enable), "r"(0u)
        : "memory");
}
__device__ __forceinline__ void mma_tf32_ts(uint32_t d_tmem, uint32_t a_tmem,
                                            uint64_t b_desc, uint32_t idesc,
                                            uint32_t enable) {
    asm volatile(
        "{\n\t.reg .pred p;\n\t"
        "setp.ne.u32 p, %4, 0;\n\t"
        "tcgen05.mma.cta_group::1.kind::tf32 [%0], [%1], %2, %3, {%5,%5,%5,%5}, p;\n\t}"
        :: "r"(d_tmem), "r"(a_tmem), "l"(b_desc), "r"(idesc), "r"(enable), "r"(0u)
        : "memory");
}
#endif  // HAS_TCGEN05

// SW128 K-major descriptor base: layout=SW128(2), version=1, SBO=64, LBO=1
static constexpr uint64_t DESC_BASE =
    (2ull << 61) | (1ull << 46) | (64ull << 32) | (1ull << 16);

__device__ __forceinline__ uint32_t sw128(uint32_t off) {
    return off ^ ((off >> 3) & 0x70);
}

// =================================================================
// GEMM (128x256 tile) — small projections (unchanged, proven)
// =================================================================
#define GK 32
#define A_BYTES 16384
#define B_BYTES 32768
#define STAGE_BYTES (A_BYTES + B_BYTES)          // 48KB
#define GEMM_SMEM   (2 * STAGE_BYTES + 1024)

__global__ __launch_bounds__(256, 2)
void gemm_tc(const float* __restrict__ A, const float* __restrict__ W,
             float* __restrict__ C, const float* __restrict__ bias,
             int M, int N, int K)
{
#if HAS_TCGEN05
    extern __shared__ char smraw[];
    __shared__ uint64_t mbar[2];
    __shared__ uint32_t tmem_slot;

    const uint32_t smbase = (smem_u32(smraw) + 1023u) & ~1023u;
    const uint32_t bar0 = smem_u32(&mbar[0]);
    const uint32_t bar1 = smem_u32(&mbar[1]);
    const uint32_t slot = smem_u32(&tmem_slot);

    const int tid = threadIdx.x;
    const int wid = tid >> 5;
    const int lid = tid & 31;
    const int m0 = blockIdx.y * 128;
    const int n0 = blockIdx.x * 256;

    if (wid == 0) TCGEN05_ALLOC(slot, 256);
    if (tid == 0) { MBARRIER_INIT(bar0, 1); MBARRIER_INIT(bar1, 1); }
    __syncthreads();
    uint32_t tmem;
    asm volatile("ld.shared.b32 %0, [%1];" : "=r"(tmem) : "r"(slot));
    if (wid == 0) TCGEN05_RELINQ();

    const uint32_t IDESC = (1u << 4) | (2u << 7) | (2u << 10)
                         | ((256u / 8) << 17) | ((128u / 16) << 24);

    const int NC = K / GK;
    int ph0 = 0, ph1 = 0;

    for (int c = 0; c < NC; c++) {
        const int buf = c & 1;
        const uint32_t barb = buf ? bar1 : bar0;
        if (c >= 2) {
            MBARRIER_WAIT_PARITY(barb, (buf ? ph1 : ph0));
            if (buf) ph1 ^= 1; else ph0 ^= 1;
        }
        const uint32_t sb = smbase + buf * STAGE_BYTES;
        const float* Ap = A + (size_t)m0 * K + c * GK;
        const float* Wp = W + (size_t)n0 * K + c * GK;

#pragma unroll
        for (int it = 0; it < 4; it++) {
            int i = tid + it * 256;
            int row = i >> 3, fo = i & 7;
            float4 v = *(const float4*)(Ap + (size_t)row * K + fo * 4);
            uint32_t r0 = f2tf32(v.x), r1 = f2tf32(v.y),
                     r2 = f2tf32(v.z), r3 = f2tf32(v.w);
            uint32_t dst = sb + sw128((uint32_t)(row * 128 + fo * 16));
            asm volatile("st.shared.v4.b32 [%0], {%1,%2,%3,%4};"
                         :: "r"(dst), "r"(r0), "r"(r1), "r"(r2), "r"(r3) : "memory");
        }
#pragma unroll
        for (int it = 0; it < 8; it++) {
            int i = tid + it * 256;
            int row = i >> 3, fo = i & 7;
            float4 v = *(const float4*)(Wp + (size_t)row * K + fo * 4);
            uint32_t r0 = f2tf32(v.x), r1 = f2tf32(v.y),
                     r2 = f2tf32(v.z), r3 = f2tf32(v.w);
            uint32_t dst = sb + A_BYTES + sw128((uint32_t)(row * 128 + fo * 16));
            asm volatile("st.shared.v4.b32 [%0], {%1,%2,%3,%4};"
                         :: "r"(dst), "r"(r0), "r"(r1), "r"(r2), "r"(r3) : "memory");
        }
        __syncthreads();

        if (wid == 0 && elect_one()) {
            FENCE_ASYNC();
            const uint64_t dA = DESC_BASE | ((uint64_t)(sb >> 4) & 0x3FFF);
            const uint64_t dB = DESC_BASE | ((uint64_t)((sb + A_BYTES) >> 4) & 0x3FFF);
#pragma unroll
            for (int k = 0; k < 4; k++) {
                uint32_t en = (c > 0 || k > 0) ? 1u : 0u;
                mma_tf32_ss(tmem, dA + k * 2, dB + k * 2, IDESC, en);
            }
            TCGEN05_COMMIT(barb);
        }
    }

    MBARRIER_WAIT_PARITY(bar0, ph0);
    MBARRIER_WAIT_PARITY(bar1, ph1);
    TCGEN05_FENCE_AFTER();

    {
        const int colh = wid >> 2;
        const int sub  = wid & 3;
        const int r = sub * 32 + lid;
        float* Crow = C + (size_t)(m0 + r) * N + n0 + colh * 128;
        const float* bp = bias ? (bias + n0 + colh * 128) : nullptr;
#pragma unroll
        for (int cb = 0; cb < 4; cb++) {
            uint32_t rr[32];
            TCGEN05_LD_X32(rr, tmem + colh * 128 + cb * 32);
            TCGEN05_WAIT_LD();
#pragma unroll
            for (int j = 0; j < 32; j += 4) {
                float4 o;
                o.x = __uint_as_float(rr[j + 0]);
                o.y = __uint_as_float(rr[j + 1]);
                o.z = __uint_as_float(rr[j + 2]);
                o.w = __uint_as_float(rr[j + 3]);
                if (bp) {
                    o.x += bp[cb * 32 + j + 0]; o.y += bp[cb * 32 + j + 1];
                    o.z += bp[cb * 32 + j + 2]; o.w += bp[cb * 32 + j + 3];
                }
                *(float4*)(Crow + cb * 32 + j) = o;
            }
        }
    }
    TCGEN05_FENCE_BEFORE();
    __syncthreads();
    if (wid == 0) TCGEN05_DEALLOC(tmem, 256);

#else
    __shared__ float As[8][128];
    __shared__ float Ws[8][128];
    const int tid  = threadIdx.x;
    const int ty   = tid >> 4;
    const int tx   = tid & 15;
    const int row0 = blockIdx.y * 128;
    const int lrow = tid >> 1;
    const int lk   = (tid & 1) * 4;

    for (int half = 0; half < 2; half++) {
        const int col0 = blockIdx.x * 256 + half * 128;
        const float* Ap = A + (size_t)(row0 + lrow) * K + lk;
        const float* Wp = W + (size_t)(col0 + lrow) * K + lk;
        float acc[8][8];
#pragma unroll
        for (int i = 0; i < 8; i++)
#pragma unroll
            for (int j = 0; j < 8; j++) acc[i][j] = 0.0f;

        for (int k0 = 0; k0 < K; k0 += 8) {
            float4 av = *(const float4*)(Ap + k0);
            float4 wv = *(const float4*)(Wp + k0);
            As[lk + 0][lrow] = av.x; As[lk + 1][lrow] = av.y;
            As[lk + 2][lrow] = av.z; As[lk + 3][lrow] = av.w;
            Ws[lk + 0][lrow] = wv.x; Ws[lk + 1][lrow] = wv.y;
            Ws[lk + 2][lrow] = wv.z; Ws[lk + 3][lrow] = wv.w;
            __syncthreads();
#pragma unroll
            for (int k = 0; k < 8; k++) {
                float a[8], b[8];
                float4 t0 = *(const float4*)(&As[k][ty * 8 + 0]);
                float4 t1 = *(const float4*)(&As[k][ty * 8 + 4]);
                a[0]=t0.x;a[1]=t0.y;a[2]=t0.z;a[3]=t0.w;a[4]=t1.x;a[5]=t1.y;a[6]=t1.z;a[7]=t1.w;
                float4 u0 = *(const float4*)(&Ws[k][tx * 8 + 0]);
                float4 u1 = *(const float4*)(&Ws[k][tx * 8 + 4]);
                b[0]=u0.x;b[1]=u0.y;b[2]=u0.z;b[3]=u0.w;b[4]=u1.x;b[5]=u1.y;b[6]=u1.z;b[7]=u1.w;
#pragma unroll
                for (int i = 0; i < 8; i++)
#pragma unroll
                    for (int j = 0; j < 8; j++) acc[i][j] += a[i] * b[j];
            }
            __syncthreads();
        }
#pragma unroll
        for (int i = 0; i < 8; i++) {
            const size_t r = (size_t)(row0 + ty * 8 + i);
#pragma unroll
            for (int j = 0; j < 8; j++) {
                const int cc = col0 + tx * 8 + j;
                float v = acc[i][j];
                if (bias) v += bias[cc];
                C[r * N + cc] = v;
            }
        }
        __syncthreads();
    }
#endif
}

// =================================================================
// GEMM (256x256 tile) — big kv projection (unchanged, proven)
// =================================================================
#define A256_BYTES 32768
#define STAGE256 (A256_BYTES + B_BYTES)          // 64KB
#define GEMM256_SMEM (2 * STAGE256 + 1024)

__global__ __launch_bounds__(256, 1)
void gemm_tc256(const float* __restrict__ A, const float* __restrict__ W,
                float* __restrict__ C, const float* __restrict__ bias,
                int M, int N, int K)
{
#if HAS_TCGEN05
    extern __shared__ char smraw[];
    __shared__ uint64_t mbar[2];
    __shared__ uint32_t tmem_slot;

    const uint32_t smbase = (smem_u32(smraw) + 1023u) & ~1023u;
    const uint32_t bar0 = smem_u32(&mbar[0]);
    const uint32_t bar1 = smem_u32(&mbar[1]);
    const uint32_t slot = smem_u32(&tmem_slot);

    const int tid = threadIdx.x;
    const int wid = tid >> 5;
    const int lid = tid & 31;
    const int m0 = blockIdx.y * 256;
    const int n0 = blockIdx.x * 256;

    if (wid == 0) TCGEN05_ALLOC(slot, 512);
    if (tid == 0) { MBARRIER_INIT(bar0, 1); MBARRIER_INIT(bar1, 1); }
    __syncthreads();
    uint32_t tmem;
    asm volatile("ld.shared.b32 %0, [%1];" : "=r"(tmem) : "r"(slot));
    if (wid == 0) TCGEN05_RELINQ();

    const uint32_t IDESC = (1u << 4) | (2u << 7) | (2u << 10)
                         | ((256u / 8) << 17) | ((128u / 16) << 24);

    const int NC = K / GK;
    int ph0 = 0, ph1 = 0;

    for (int c = 0; c < NC; c++) {
        const int buf = c & 1;
        const uint32_t barb = buf ? bar1 : bar0;
        if (c >= 2) {
            MBARRIER_WAIT_PARITY(barb, (buf ? ph1 : ph0));
            if (buf) ph1 ^= 1; else ph0 ^= 1;
        }
        const uint32_t sb = smbase + buf * STAGE256;
        const float* Ap = A + (size_t)m0 * K + c * GK;
        const float* Wp = W + (size_t)n0 * K + c * GK;

#pragma unroll
        for (int it = 0; it < 8; it++) {
            int i = tid + it * 256;
            int row = i >> 3, fo = i & 7;
            float4 v = *(const float4*)(Ap + (size_t)row * K + fo * 4);
            uint32_t r0 = f2tf32(v.x), r1 = f2tf32(v.y),
                     r2 = f2tf32(v.z), r3 = f2tf32(v.w);
            uint32_t off = sw128((uint32_t)((row & 127) * 128 + fo * 16));
            uint32_t dst = sb + ((row < 128) ? 0u : 16384u) + off;
            asm volatile("st.shared.v4.b32 [%0], {%1,%2,%3,%4};"
                         :: "r"(dst), "r"(r0), "r"(r1), "r"(r2), "r"(r3) : "memory");
        }
#pragma unroll
        for (int it = 0; it < 8; it++) {
            int i = tid + it * 256;
            int row = i >> 3, fo = i & 7;
            float4 v = *(const float4*)(Wp + (size_t)row * K + fo * 4);
            uint32_t r0 = f2tf32(v.x), r1 = f2tf32(v.y),
                     r2 = f2tf32(v.z), r3 = f2tf32(v.w);
            uint32_t dst = sb + A256_BYTES + sw128((uint32_t)(row * 128 + fo * 16));
            asm volatile("st.shared.v4.b32 [%0], {%1,%2,%3,%4};"
                         :: "r"(dst), "r"(r0), "r"(r1), "r"(r2), "r"(r3) : "memory");
        }
        __syncthreads();

        if (wid == 0 && elect_one()) {
            FENCE_ASYNC();
            const uint64_t dA0 = DESC_BASE | ((uint64_t)(sb >> 4) & 0x3FFF);
            const uint64_t dA1 = DESC_BASE | ((uint64_t)((sb + 16384u) >> 4) & 0x3FFF);
            const uint64_t dB  = DESC_BASE | ((uint64_t)((sb + A256_BYTES) >> 4) & 0x3FFF);
#pragma unroll
            for (int k = 0; k < 4; k++) {
                uint32_t en = (c > 0 || k > 0) ? 1u : 0u;
                mma_tf32_ss(tmem,       dA0 + k * 2, dB + k * 2, IDESC, en);
                mma_tf32_ss(tmem + 256, dA1 + k * 2, dB + k * 2, IDESC, en);
            }
            TCGEN05_COMMIT(barb);
        }
    }

    MBARRIER_WAIT_PARITY(bar0, ph0);
    MBARRIER_WAIT_PARITY(bar1, ph1);
    TCGEN05_FENCE_AFTER();

    {
        const int tile = wid >> 2;
        const uint32_t dbase = tmem + tile * 256;
        const int rowl = (wid & 3) * 32 + lid;
        const size_t grow = (size_t)m0 + tile * 128 + rowl;
        float* Crow = C + grow * N + n0;
        const float* bp = bias ? (bias + n0) : nullptr;
#pragma unroll
        for (int cb = 0; cb < 8; cb++) {
            uint32_t rr[32];
            TCGEN05_LD_X32(rr, dbase + cb * 32);
            TCGEN05_WAIT_LD();
#pragma unroll
            for (int j = 0; j < 32; j += 4) {
                float4 o;
                o.x = __uint_as_float(rr[j + 0]);
                o.y = __uint_as_float(rr[j + 1]);
                o.z = __uint_as_float(rr[j + 2]);
                o.w = __uint_as_float(rr[j + 3]);
                if (bp) {
                    o.x += bp[cb * 32 + j + 0]; o.y += bp[cb * 32 + j + 1];
                    o.z += bp[cb * 32 + j + 2]; o.w += bp[cb * 32 + j + 3];
                }
                *(float4*)(Crow + cb * 32 + j) = o;
            }
        }
    }
    TCGEN05_FENCE_BEFORE();
    __syncthreads();
    if (wid == 0) TCGEN05_DEALLOC(tmem, 512);

#else
    __shared__ float As[8][128];
    __shared__ float Ws[8][128];
    const int tid  = threadIdx.x;
    const int ty   = tid >> 4;
    const int tx   = tid & 15;
    const int lrow = tid >> 1;
    const int lk   = (tid & 1) * 4;

    for (int hm = 0; hm < 2; hm++)
    for (int hn = 0; hn < 2; hn++) {
        const int row0 = blockIdx.y * 256 + hm * 128;
        const int col0 = blockIdx.x * 256 + hn * 128;
        const float* Ap = A + (size_t)(row0 + lrow) * K + lk;
        const float* Wp = W + (size_t)(col0 + lrow) * K + lk;
        float acc[8][8];
#pragma unroll
        for (int i = 0; i < 8; i++)
#pragma unroll
            for (int j = 0; j < 8; j++) acc[i][j] = 0.0f;

        for (int k0 = 0; k0 < K; k0 += 8) {
            float4 av = *(const float4*)(Ap + k0);
            float4 wv = *(const float4*)(Wp + k0);
            As[lk + 0][lrow] = av.x; As[lk + 1][lrow] = av.y;
            As[lk + 2][lrow] = av.z; As[lk + 3][lrow] = av.w;
            Ws[lk + 0][lrow] = wv.x; Ws[lk + 1][lrow] = wv.y;
            Ws[lk + 2][lrow] = wv.z; Ws[lk + 3][lrow] = wv.w;
            __syncthreads();
#pragma unroll
            for (int k = 0; k < 8; k++) {
                float a[8], b[8];
                float4 t0 = *(const float4*)(&As[k][ty * 8 + 0]);
                float4 t1 = *(const float4*)(&As[k][ty * 8 + 4]);
                a[0]=t0.x;a[1]=t0.y;a[2]=t0.z;a[3]=t0.w;a[4]=t1.x;a[5]=t1.y;a[6]=t1.z;a[7]=t1.w;
                float4 u0 = *(const float4*)(&Ws[k][tx * 8 + 0]);
                float4 u1 = *(const float4*)(&Ws[k][tx * 8 + 4]);
                b[0]=u0.x;b[1]=u0.y;b[2]=u0.z;b[3]=u0.w;b[4]=u1.x;b[5]=u1.y;b[6]=u1.z;b[7]=u1.w;
#pragma unroll
                for (int i = 0; i < 8; i++)
#pragma unroll
                    for (int j = 0; j < 8; j++) acc[i][j] += a[i] * b[j];
            }
            __syncthreads();
        }
#pragma unroll
        for (int i = 0; i < 8; i++) {
            const size_t r = (size_t)(row0 + ty * 8 + i);
#pragma unroll
            for (int j = 0; j < 8; j++) {
                const int cc = col0 + tx * 8 + j;
                float v = acc[i][j];
                if (bias) v += bias[cc];
                C[r * N + cc] = v;
            }
        }
        __syncthreads();
    }
#endif
}

// =================================================================
// V^T pre-pass (unchanged, proven)
// =================================================================
__global__ void vt_transpose(const float* __restrict__ kv, float* __restrict__ vt)
{
    __shared__ float ts[32][33];
    const int bh = blockIdx.z;
    const int b = bh >> 4, h = bh & 15;
    const int s0 = blockIdx.x * 32;
    const int d0 = blockIdx.y * 32;
    const int tx = threadIdx.x, ty = threadIdx.y;

    const float* src = kv + ((size_t)b * SEQ) * (2 * DIM) + DIM + h * HDIM;
#pragma unroll
    for (int k = 0; k < 4; k++) {
        int s = s0 + ty + k * 8;
        ts[ty + k * 8][tx] = src[(size_t)s * (2 * DIM) + d0 + tx];
    }
    __syncthreads();
    float* dst = vt + ((size_t)bh * HDIM) * SEQ;
#pragma unroll
    for (int k = 0; k < 4; k++) {
        int d = d0 + ty + k * 8;
        dst[(size_t)d * SEQ + s0 + tx] = __uint_as_float(f2tf32(ts[tx][ty + k * 8]));
    }
}

// =================================================================
// Fully-pipelined tensor-core flash attention. 2 CTAs/SM.
// SCHUNK=64. Q resident in TMEM (TS-mode QK). SP double-buffered,
// K double-buffered, VT triple-buffered.
// smem: K 2x16K | VT 3x16K = 80KB
// TMEM: Q @0 (64) | SP0 @64 (64) | SP1 @128 (64) | O @192 (64)
// =================================================================
#define SCHUNK 64
#define NCH (SEQ / SCHUNK)                 // 128
#define KTILE_B 16384
#define ATTN_SMEM (5 * 16384 + 1024)       // 81KB
#define SCALE_L2E 0.18033688011112042f     // SCALE * log2(e)

__global__ __launch_bounds__(256, 2)
void attn_tc(const float* __restrict__ q, const float* __restrict__ kv,
             const float* __restrict__ vt, float* __restrict__ out)
{
#if HAS_TCGEN05
    extern __shared__ char smraw[];
    __shared__ uint64_t mbar[2];
    __shared__ uint32_t tmem_slot;
    __shared__ float ls_sh[256];

    const uint32_t smbase = (smem_u32(smraw) + 1023u) & ~1023u;
    const uint32_t Kb[2]  = { smbase, smbase + 16384u };
    const uint32_t Vb[3]  = { smbase + 32768u, smbase + 49152u, smbase + 65536u };
    const uint32_t barQK = smem_u32(&mbar[0]);
    const uint32_t barPV = smem_u32(&mbar[1]);
    const uint32_t slot  = smem_u32(&tmem_slot);

    const int tid = threadIdx.x;
    const int wid = tid >> 5;
    const int lid = tid & 31;
    const int bh  = blockIdx.x >> 2;
    const int lt  = blockIdx.x & 3;
    const int b   = bh >> 4, h = bh & 15;
    const int l0  = lt * 128;

    if (wid == 0) TCGEN05_ALLOC(slot, 256);
    if (tid == 0) { MBARRIER_INIT(barQK, 1); MBARRIER_INIT(barPV, 1); }
    __syncthreads();
    uint32_t tmem;
    asm volatile("ld.shared.b32 %0, [%1];" : "=r"(tmem) : "r"(slot));
    if (wid == 0) TCGEN05_RELINQ();
    const uint32_t tmem_Q  = tmem;
    const uint32_t tmem_SP = tmem + 64;      // SP[buf] = tmem_SP + buf*64
    const uint32_t tmem_O  = tmem + 192;

    // N=64, M=128, tf32
    const uint32_t IDESC64 = (1u << 4) | (2u << 7) | (2u << 10)
                           | ((64u / 8) << 17) | ((128u / 16) << 24);

    const float* kbase = kv + (size_t)b * SEQ * (2 * DIM) + h * HDIM;
    const float* vbase = vt + ((size_t)bh * HDIM) * SEQ;

    // ---- Q -> TMEM (scaled+rounded). warp w: rows (w&3)*32+lid, cols (w>>2)*32 ----
    {
        const int r = (wid & 3) * 32 + lid;
        const int c0 = (wid >> 2) * 32;
        const float* qp = q + ((size_t)b * LAT + l0 + r) * DIM + h * HDIM + c0;
        uint32_t rr[32];
#pragma unroll
        for (int j = 0; j < 32; j += 4) {
            float4 v = *(const float4*)(qp + j);
            rr[j + 0] = f2tf32(v.x * SCALE_L2E);
            rr[j + 1] = f2tf32(v.y * SCALE_L2E);
            rr[j + 2] = f2tf32(v.z * SCALE_L2E);
            rr[j + 3] = f2tf32(v.w * SCALE_L2E);
        }
        TCGEN05_ST_X32(tmem_Q + c0 + ((uint32_t)(wid & 3) << 21), rr);
        TCGEN05_WAIT_ST();
    }

    // ---- loaders (K tile: 64 keys x 64 dims; VT tile: 64 d x 64 s) ----
    auto loadK = [&](int ci, uint32_t dstb) {
        const int s0 = ci * SCHUNK;
#pragma unroll
        for (int it = 0; it < 4; it++) {
            int i = tid + it * 256;              // 1024 f4
            int kr = i >> 4, f = i & 15;
            int kc = f >> 3, fo = f & 7;
            float4 v = *(const float4*)(kbase + (size_t)(s0 + kr) * (2 * DIM) + f * 4);
            uint32_t r0 = f2tf32(v.x), r1 = f2tf32(v.y),
                     r2 = f2tf32(v.z), r3 = f2tf32(v.w);
            uint32_t dst = dstb + kc * 8192u + sw128((uint32_t)(kr * 128 + fo * 16));
            asm volatile("st.shared.v4.b32 [%0], {%1,%2,%3,%4};"
                         :: "r"(dst), "r"(r0), "r"(r1), "r"(r2), "r"(r3) : "memory");
        }
    };
    auto loadVT = [&](int ci, uint32_t dstb) {
        const int s0 = ci * SCHUNK;
#pragma unroll
        for (int it = 0; it < 4; it++) {
            int i = tid + it * 256;              // 1024 f4
            int d = i >> 4, f = i & 15;
            int sc = f >> 3, fo = f & 7;
            float4 v = *(const float4*)(vbase + (size_t)d * SEQ + s0 + f * 4);
            uint32_t dst = dstb + sc * 8192u + sw128((uint32_t)(d * 128 + fo * 16));
            asm volatile("st.shared.v4.b32 [%0], {%1,%2,%3,%4};"
                         :: "r"(dst), "r"(__float_as_uint(v.x)), "r"(__float_as_uint(v.y)),
                            "r"(__float_as_uint(v.z)), "r"(__float_as_uint(v.w)) : "memory");
        }
    };

    auto issueQK = [&](int ci, uint32_t sp) {
        const uint32_t kb = Kb[ci & 1];
#pragma unroll
        for (int st = 0; st < 8; st++) {
            const uint64_t dk = (DESC_BASE
                | ((uint64_t)((kb + (st >> 2) * 8192u) >> 4) & 0x3FFF)) + (st & 3) * 2;
            mma_tf32_ts(sp, tmem_Q + st * 8, dk, IDESC64, st > 0 ? 1u : 0u);
        }
        TCGEN05_COMMIT(barQK);
    };

    // ---- prologue: K(0),K(1),VT(0),VT(1); QK(0) ----
    loadK(0, Kb[0]); loadK(1, Kb[1]);
    loadVT(0, Vb[0]); loadVT(1, Vb[1]);
    TCGEN05_FENCE_BEFORE();
    __syncthreads();
    if (wid == 0 && elect_one()) {
        FENCE_ASYNC();
        TCGEN05_FENCE_AFTER();
        issueQK(0, tmem_SP);
    }

    float lsum = 0.0f;
    int phQK = 0, phPV = 0;
    const uint32_t colofs = (uint32_t)(wid >> 2) * 32u;
    const uint32_t wlane  = (uint32_t)(wid & 3) << 21;

    for (int ci = 0; ci < NCH; ci++) {
        const int buf = ci & 1;
        const uint32_t sp = tmem_SP + (uint32_t)buf * 64u;

        // 1) wait QK(ci) — covered by prior iteration's work
        MBARRIER_WAIT_PARITY(barQK, phQK); phQK ^= 1;
        TCGEN05_FENCE_AFTER();

        // 2) softmax: S(ci) -> P in place (warp: 32 rows x 32 cols)
        {
            uint32_t rr[32];
            TCGEN05_LD_X32(rr, sp + colofs);
            TCGEN05_WAIT_LD();
#pragma unroll
            for (int j = 0; j < 32; j++) {
                float p;
                asm("ex2.approx.f32 %0, %1;" : "=f"(p) : "f"(__uint_as_float(rr[j])));
                lsum += p;
                rr[j] = f2tf32(p);
            }
            TCGEN05_ST_X32(sp + wlane + colofs, rr);
            TCGEN05_WAIT_ST();
        }
        TCGEN05_FENCE_BEFORE();

        // 3) retire PV(ci-1) (covered by softmax) — frees SP[buf^1], VT[(ci-1)%3]
        if (ci >= 1) { MBARRIER_WAIT_PARITY(barPV, phPV); phPV ^= 1; }

        // 4) issue QK(ci+1) into SP[buf^1] (K(ci+1) loaded & sync'd last iter)
        if (ci + 1 < NCH && wid == 0 && elect_one()) {
            FENCE_ASYNC();
            TCGEN05_FENCE_AFTER();
            issueQK(ci + 1, tmem_SP + (uint32_t)(buf ^ 1) * 64u);
        }

        // 5) prefetch chunk ci+2 (K[buf] free: QK(ci) retired; VT slot free: PV(ci-1) retired)
        if (ci + 2 < NCH) {
            loadK(ci + 2, Kb[buf]);
            loadVT(ci + 2, Vb[(ci + 2) % 3]);
        }

        // 6) one sync: P stores + smem prefetch visible to all
        __syncthreads();

        // 7) issue PV(ci): O += P[buf] @ VT[ci%3]
        if (wid == 0 && elect_one()) {
            TCGEN05_FENCE_AFTER();
            FENCE_ASYNC();
            const uint32_t vb = Vb[ci % 3];
#pragma unroll
            for (int st = 0; st < 8; st++) {
                const uint64_t dv = (DESC_BASE
                    | ((uint64_t)((vb + (st >> 2) * 8192u) >> 4) & 0x3FFF)) + (st & 3) * 2;
                mma_tf32_ts(tmem_O, sp + st * 8, dv, IDESC64,
                            (ci > 0 || st > 0) ? 1u : 0u);
            }
            TCGEN05_COMMIT(barPV);
        }
    }

    // drain last PV
    MBARRIER_WAIT_PARITY(barPV, phPV);
    TCGEN05_FENCE_AFTER();

    // ---- merge lsum partials, epilogue ----
    ls_sh[tid] = lsum;
    __syncthreads();

    if (wid < 4) {
        const int r = wid * 32 + lid;
        const float inv = 1.0f / (ls_sh[tid] + ls_sh[tid + 128]);
        float* op = out + ((size_t)b * LAT + l0 + r) * DIM + h * HDIM;
#pragma unroll
        for (int cb = 0; cb < 2; cb++) {
            uint32_t rr[32];
            TCGEN05_LD_X32(rr, tmem_O + cb * 32);
            TCGEN05_WAIT_LD();
#pragma unroll
            for (int j = 0; j < 32; j += 4) {
                float4 o;
                o.x = __uint_as_float(rr[j + 0]) * inv;
                o.y = __uint_as_float(rr[j + 1]) * inv;
                o.z = __uint_as_float(rr[j + 2]) * inv;
                o.w = __uint_as_float(rr[j + 3]) * inv;
                *(float4*)(op + cb * 32 + j) = o;
            }
        }
    }
    TCGEN05_FENCE_BEFORE();
    __syncthreads();
    if (wid == 0) TCGEN05_DEALLOC(tmem, 256);

#else
    // SIMT fallback (thread-per-row; never runs on GB300)
    const int tid = threadIdx.x;
    const int bh  = blockIdx.x >> 2;
    const int lt  = blockIdx.x & 3;
    const int b   = bh >> 4, h = bh & 15;
    const int l0  = lt * 128;
    if (tid < 128) {
        const float* qrow = q + ((size_t)b * LAT + l0 + tid) * DIM + h * HDIM;
        const float* kb = kv + (size_t)b * SEQ * (2 * DIM) + h * HDIM;
        float qr[64];
#pragma unroll
        for (int d = 0; d < 64; d++) qr[d] = qrow[d] * SCALE;
        float O[64];
#pragma unroll
        for (int d = 0; d < 64; d++) O[d] = 0.0f;
        float l = 0.0f;
        for (int s = 0; s < SEQ; s++) {
            const float* kr = kb + (size_t)s * (2 * DIM);
            float sv = 0.0f;
#pragma unroll 16
            for (int d = 0; d < 64; d++) sv += qr[d] * kr[d];
            float p = __expf(sv);
            l += p;
            const float* vr = kr + DIM;
#pragma unroll 16
            for (int d = 0; d < 64; d++) O[d] += p * vr[d];
        }
        float* op = out + ((size_t)b * LAT + l0 + tid) * DIM + h * HDIM;
        float inv = 1.0f / l;
#pragma unroll
        for (int d = 0; d < 64; d++) op[d] = O[d] * inv;
    }
#endif
}

// =================================================================
// launch
// =================================================================
extern "C" void kernel_launch(void* const* d_in, const int* in_sizes, int n_in,
                              void* d_out, int out_size)
{
    const float* x       = (const float*)d_in[0];
    const float* latents = (const float*)d_in[1];
    if (in_sizes[0] != BATCH * SEQ * DIM) {
        x       = (const float*)d_in[1];
        latents = (const float*)d_in[0];
    }
    const float* w_q   = (const float*)d_in[2];
    const float* w_kv  = (const float*)d_in[3];
    const float* w_out = (const float*)d_in[4];
    const float* b_out = (const float*)d_in[5];
    float* out = (float*)d_out;

    float *q, *kvbuf, *att, *vt;
    cudaGetSymbolAddress((void**)&q,     g_q);
    cudaGetSymbolAddress((void**)&kvbuf, g_kv);
    cudaGetSymbolAddress((void**)&att,   g_att);
    cudaGetSymbolAddress((void**)&vt,    g_vt);

    const int M_q  = BATCH * LAT;    // 2048
    const int M_kv = BATCH * SEQ;    // 32768

    cudaFuncSetAttribute(gemm_tc,    cudaFuncAttributeMaxDynamicSharedMemorySize, GEMM_SMEM);
    cudaFuncSetAttribute(gemm_tc256, cudaFuncAttributeMaxDynamicSharedMemorySize, GEMM256_SMEM);
    cudaFuncSetAttribute(attn_tc,    cudaFuncAttributeMaxDynamicSharedMemorySize, ATTN_SMEM);

    // 1) q = latents @ w_q^T        (2048 x 1024)
    gemm_tc<<<dim3(DIM / 256, M_q / 128), 256, GEMM_SMEM>>>(latents, w_q, q, nullptr,
                                                            M_q, DIM, DIM);
    // 2) kv = x @ w_kv^T            (32768 x 2048)
    gemm_tc256<<<dim3(2 * DIM / 256, M_kv / 256), 256, GEMM256_SMEM>>>(
        x, w_kv, kvbuf, nullptr, M_kv, 2 * DIM, DIM);
    // 3) V^T (tf32) pre-pass
    vt_transpose<<<dim3(SEQ / 32, HDIM / 32, BATCH * NHEADS), dim3(32, 8)>>>(kvbuf, vt);
    // 4) attention
    attn_tc<<<BATCH * NHEADS * (LAT / 128), 256, ATTN_SMEM>>>(q, kvbuf, vt, att);
    // 5) out = att @ w_out^T + b_out
    gemm_tc<<<dim3(DIM / 256, M_q / 128), 256, GEMM_SMEM>>>(att, w_out, out, b_out,
                                                            M_q, DIM, DIM);
}

// round 11
// speedup vs baseline: 1.1157x; 1.1157x over previous
#include <cuda_runtime.h>
#include <cstdint>
#include <math.h>

#define DIM       1024
#define NHEADS    16
#define HDIM      64
#define BATCH     4
#define SEQ       8192
#define LAT       512
#define SCALE     0.125f   // 64^-0.5

#if defined(__CUDA_ARCH_FEAT_SM103_ALL) || defined(__CUDA_ARCH_FEAT_SM100_ALL) || \
    (defined(__CUDA_ARCH_SPECIFIC__) && (__CUDA_ARCH_SPECIFIC__ >= 1000))
#define HAS_TCGEN05 1
#else
#define HAS_TCGEN05 0
#endif

// -------- scratch (device globals; no allocation allowed) --------
__device__ float g_q  [(size_t)BATCH * LAT * DIM];                    // 8 MB
__device__ float g_kv [(size_t)BATCH * SEQ * 2 * DIM];                // 268 MB (V half unused)
__device__ float g_att[(size_t)BATCH * LAT * DIM];                    // 8 MB
__device__ float g_vt [(size_t)BATCH * NHEADS * HDIM * SEQ];          // 134 MB (V^T, tf32)

// ================= helpers =================
__device__ __forceinline__ uint32_t smem_u32(const void* p) {
    uint32_t a;
    asm("{ .reg .u64 t; cvta.to.shared.u64 t, %1; cvt.u32.u64 %0, t; }"
        : "=r"(a) : "l"(p));
    return a;
}
__device__ __forceinline__ uint32_t f2tf32(float f) {
    uint32_t r;
    asm("cvt.rna.tf32.f32 %0, %1;" : "=r"(r) : "f"(f));
    return r;
}

#if HAS_TCGEN05
__device__ __forceinline__ uint32_t elect_one() {
    uint32_t p;
    asm volatile("{ .reg .pred p; elect.sync _|p, 0xFFFFFFFF; selp.b32 %0,1,0,p; }"
                 : "=r"(p));
    return p;
}

#define MBARRIER_INIT(addr, cnt) \
    asm volatile("mbarrier.init.shared.b64 [%0], %1;" :: "r"(addr), "r"(cnt) : "memory")

#define MBARRIER_WAIT_PARITY(mbar, par) do {                                   \
    uint32_t _m = (mbar); uint32_t _p = (par); uint32_t _done;                 \
    asm volatile("{\n\t.reg .pred p;\n\t"                                      \
        "mbarrier.try_wait.parity.acquire.cta.shared::cta.b64 p, [%1], %2;\n\t"\
        "selp.b32 %0, 1, 0, p;\n\t}"                                           \
        : "=r"(_done) : "r"(_m), "r"(_p) : "memory");                          \
    if (!_done) {                                                              \
        asm volatile("{\n\t.reg .pred P1;\n\t"                                 \
            "WL_%=:\n\t"                                                       \
            "mbarrier.try_wait.parity.acquire.cta.shared::cta.b64 P1, [%0], %1, 0x989680;\n\t" \
            "@P1 bra.uni WD_%=;\n\t"                                           \
            "bra.uni WL_%=;\n\t"                                               \
            "WD_%=:\n\t}"                                                      \
            :: "r"(_m), "r"(_p) : "memory");                                   \
    }                                                                          \
} while (0)

#define TCGEN05_ALLOC(slot, n) \
    asm volatile("tcgen05.alloc.cta_group::1.sync.aligned.shared::cta.b32 [%0], %1;" \
                 :: "r"(slot), "r"(n) : "memory")
#define TCGEN05_DEALLOC(tm, n) \
    asm volatile("tcgen05.dealloc.cta_group::1.sync.aligned.b32 %0, %1;" :: "r"(tm), "r"(n))
#define TCGEN05_RELINQ() \
    asm volatile("tcgen05.relinquish_alloc_permit.cta_group::1.sync.aligned;")
#define TCGEN05_COMMIT(mbar) \
    asm volatile("tcgen05.commit.cta_group::1.mbarrier::arrive::one.shared::cluster.b64 [%0];" \
                 :: "r"(mbar) : "memory")
#define TCGEN05_WAIT_LD() asm volatile("tcgen05.wait::ld.sync.aligned;" ::: "memory")
#define TCGEN05_WAIT_ST() asm volatile("tcgen05.wait::st.sync.aligned;" ::: "memory")
#define TCGEN05_FENCE_AFTER() asm volatile("tcgen05.fence::after_thread_sync;" ::: "memory")
#define TCGEN05_FENCE_BEFORE() asm volatile("tcgen05.fence::before_thread_sync;" ::: "memory")
#define FENCE_ASYNC() asm volatile("fence.proxy.async.shared::cta;" ::: "memory")

#define TCGEN05_LD_X32(r, addr)                                                \
    asm volatile("tcgen05.ld.sync.aligned.32x32b.x32.b32 "                     \
        "{%0,%1,%2,%3,%4,%5,%6,%7,%8,%9,%10,%11,%12,%13,%14,%15,"              \
        "%16,%17,%18,%19,%20,%21,%22,%23,%24,%25,%26,%27,%28,%29,%30,%31}, [%32];" \
        : "=r"((r)[0]),"=r"((r)[1]),"=r"((r)[2]),"=r"((r)[3]),                 \
          "=r"((r)[4]),"=r"((r)[5]),"=r"((r)[6]),"=r"((r)[7]),                 \
          "=r"((r)[8]),"=r"((r)[9]),"=r"((r)[10]),"=r"((r)[11]),               \
          "=r"((r)[12]),"=r"((r)[13]),"=r"((r)[14]),"=r"((r)[15]),             \
          "=r"((r)[16]),"=r"((r)[17]),"=r"((r)[18]),"=r"((r)[19]),             \
          "=r"((r)[20]),"=r"((r)[21]),"=r"((r)[22]),"=r"((r)[23]),             \
          "=r"((r)[24]),"=r"((r)[25]),"=r"((r)[26]),"=r"((r)[27]),             \
          "=r"((r)[28]),"=r"((r)[29]),"=r"((r)[30]),"=r"((r)[31])              \
        : "r"(addr))

#define TCGEN05_ST_X32(addr, r)                                                \
    asm volatile("tcgen05.st.sync.aligned.32x32b.x32.b32 [%0], "               \
        "{%1,%2,%3,%4,%5,%6,%7,%8,%9,%10,%11,%12,%13,%14,%15,%16,"             \
        "%17,%18,%19,%20,%21,%22,%23,%24,%25,%26,%27,%28,%29,%30,%31,%32};"    \
        :: "r"(addr),                                                          \
           "r"((r)[0]),"r"((r)[1]),"r"((r)[2]),"r"((r)[3]),                    \
           "r"((r)[4]),"r"((r)[5]),"r"((r)[6]),"r"((r)[7]),                    \
           "r"((r)[8]),"r"((r)[9]),"r"((r)[10]),"r"((r)[11]),                  \
           "r"((r)[12]),"r"((r)[13]),"r"((r)[14]),"r"((r)[15]),                \
           "r"((r)[16]),"r"((r)[17]),"r"((r)[18]),"r"((r)[19]),                \
           "r"((r)[20]),"r"((r)[21]),"r"((r)[22]),"r"((r)[23]),                \
           "r"((r)[24]),"r"((r)[25]),"r"((r)[26]),"r"((r)[27]),                \
           "r"((r)[28]),"r"((r)[29]),"r"((r)[30]),"r"((r)[31])                 \
        : "memory")

__device__ __forceinline__ void mma_tf32_ss(uint32_t d_tmem, uint64_t a_desc,
                                            uint64_t b_desc, uint32_t idesc,
                                            uint32_t enable) {
    asm volatile(
        "{\n\t.reg .pred p;\n\t"
        "setp.ne.u32 p, %4, 0;\n\t"
        "tcgen05.mma.cta_group::1.kind::tf32 [%0], %1, %2, %3, {%5,%5,%5,%5}, p;\n\t}"
        :: "r"(d_tmem), "l"(a_desc), "l"(b_desc), "r"(idesc), "r"(enable), "r"(0u)
        : "memory");
}
__device__ __forceinline__ void mma_tf32_ts(uint32_t d_tmem, uint32_t a_tmem,
                                            uint64_t b_desc, uint32_t idesc,
                                            uint32_t enable) {
    asm volatile(
        "{\n\t.reg .pred p;\n\t"
        "setp.ne.u32 p, %4, 0;\n\t"
        "tcgen05.mma.cta_group::1.kind::tf32 [%0], [%1], %2, %3, {%5,%5,%5,%5}, p;\n\t}"
        :: "r"(d_tmem), "r"(a_tmem), "l"(b_desc), "r"(idesc), "r"(enable), "r"(0u)
        : "memory");
}
#endif  // HAS_TCGEN05

// SW128 K-major descriptor base: layout=SW128(2), version=1, SBO=64, LBO=1
static constexpr uint64_t DESC_BASE =
    (2ull << 61) | (1ull << 46) | (64ull << 32) | (1ull << 16);

__device__ __forceinline__ uint32_t sw128(uint32_t off) {
    return off ^ ((off >> 3) & 0x70);
}

// =================================================================
// GEMM (128x256 tile) — small projections (unchanged, proven)
// =================================================================
#define GK 32
#define A_BYTES 16384
#define B_BYTES 32768
#define STAGE_BYTES (A_BYTES + B_BYTES)          // 48KB
#define GEMM_SMEM   (2 * STAGE_BYTES + 1024)

__global__ __launch_bounds__(256, 2)
void gemm_tc(const float* __restrict__ A, const float* __restrict__ W,
             float* __restrict__ C, const float* __restrict__ bias,
             int M, int N, int K)
{
#if HAS_TCGEN05
    extern __shared__ char smraw[];
    __shared__ uint64_t mbar[2];
    __shared__ uint32_t tmem_slot;

    const uint32_t smbase = (smem_u32(smraw) + 1023u) & ~1023u;
    const uint32_t bar0 = smem_u32(&mbar[0]);
    const uint32_t bar1 = smem_u32(&mbar[1]);
    const uint32_t slot = smem_u32(&tmem_slot);

    const int tid = threadIdx.x;
    const int wid = tid >> 5;
    const int lid = tid & 31;
    const int m0 = blockIdx.y * 128;
    const int n0 = blockIdx.x * 256;

    if (wid == 0) TCGEN05_ALLOC(slot, 256);
    if (tid == 0) { MBARRIER_INIT(bar0, 1); MBARRIER_INIT(bar1, 1); }
    __syncthreads();
    uint32_t tmem;
    asm volatile("ld.shared.b32 %0, [%1];" : "=r"(tmem) : "r"(slot));
    if (wid == 0) TCGEN05_RELINQ();

    const uint32_t IDESC = (1u << 4) | (2u << 7) | (2u << 10)
                         | ((256u / 8) << 17) | ((128u / 16) << 24);

    const int NC = K / GK;
    int ph0 = 0, ph1 = 0;

    for (int c = 0; c < NC; c++) {
        const int buf = c & 1;
        const uint32_t barb = buf ? bar1 : bar0;
        if (c >= 2) {
            MBARRIER_WAIT_PARITY(barb, (buf ? ph1 : ph0));
            if (buf) ph1 ^= 1; else ph0 ^= 1;
        }
        const uint32_t sb = smbase + buf * STAGE_BYTES;
        const float* Ap = A + (size_t)m0 * K + c * GK;
        const float* Wp = W + (size_t)n0 * K + c * GK;

#pragma unroll
        for (int it = 0; it < 4; it++) {
            int i = tid + it * 256;
            int row = i >> 3, fo = i & 7;
            float4 v = *(const float4*)(Ap + (size_t)row * K + fo * 4);
            uint32_t r0 = f2tf32(v.x), r1 = f2tf32(v.y),
                     r2 = f2tf32(v.z), r3 = f2tf32(v.w);
            uint32_t dst = sb + sw128((uint32_t)(row * 128 + fo * 16));
            asm volatile("st.shared.v4.b32 [%0], {%1,%2,%3,%4};"
                         :: "r"(dst), "r"(r0), "r"(r1), "r"(r2), "r"(r3) : "memory");
        }
#pragma unroll
        for (int it = 0; it < 8; it++) {
            int i = tid + it * 256;
            int row = i >> 3, fo = i & 7;
            float4 v = *(const float4*)(Wp + (size_t)row * K + fo * 4);
            uint32_t r0 = f2tf32(v.x), r1 = f2tf32(v.y),
                     r2 = f2tf32(v.z), r3 = f2tf32(v.w);
            uint32_t dst = sb + A_BYTES + sw128((uint32_t)(row * 128 + fo * 16));
            asm volatile("st.shared.v4.b32 [%0], {%1,%2,%3,%4};"
                         :: "r"(dst), "r"(r0), "r"(r1), "r"(r2), "r"(r3) : "memory");
        }
        __syncthreads();

        if (wid == 0 && elect_one()) {
            FENCE_ASYNC();
            const uint64_t dA = DESC_BASE | ((uint64_t)(sb >> 4) & 0x3FFF);
            const uint64_t dB = DESC_BASE | ((uint64_t)((sb + A_BYTES) >> 4) & 0x3FFF);
#pragma unroll
            for (int k = 0; k < 4; k++) {
                uint32_t en = (c > 0 || k > 0) ? 1u : 0u;
                mma_tf32_ss(tmem, dA + k * 2, dB + k * 2, IDESC, en);
            }
            TCGEN05_COMMIT(barb);
        }
    }

    MBARRIER_WAIT_PARITY(bar0, ph0);
    MBARRIER_WAIT_PARITY(bar1, ph1);
    TCGEN05_FENCE_AFTER();

    {
        const int colh = wid >> 2;
        const int sub  = wid & 3;
        const int r = sub * 32 + lid;
        float* Crow = C + (size_t)(m0 + r) * N + n0 + colh * 128;
        const float* bp = bias ? (bias + n0 + colh * 128) : nullptr;
#pragma unroll
        for (int cb = 0; cb < 4; cb++) {
            uint32_t rr[32];
            TCGEN05_LD_X32(rr, tmem + colh * 128 + cb * 32);
            TCGEN05_WAIT_LD();
#pragma unroll
            for (int j = 0; j < 32; j += 4) {
                float4 o;
                o.x = __uint_as_float(rr[j + 0]);
                o.y = __uint_as_float(rr[j + 1]);
                o.z = __uint_as_float(rr[j + 2]);
                o.w = __uint_as_float(rr[j + 3]);
                if (bp) {
                    o.x += bp[cb * 32 + j + 0]; o.y += bp[cb * 32 + j + 1];
                    o.z += bp[cb * 32 + j + 2]; o.w += bp[cb * 32 + j + 3];
                }
                *(float4*)(Crow + cb * 32 + j) = o;
            }
        }
    }
    TCGEN05_FENCE_BEFORE();
    __syncthreads();
    if (wid == 0) TCGEN05_DEALLOC(tmem, 256);

#else
    __shared__ float As[8][128];
    __shared__ float Ws[8][128];
    const int tid  = threadIdx.x;
    const int ty   = tid >> 4;
    const int tx   = tid & 15;
    const int row0 = blockIdx.y * 128;
    const int lrow = tid >> 1;
    const int lk   = (tid & 1) * 4;

    for (int half = 0; half < 2; half++) {
        const int col0 = blockIdx.x * 256 + half * 128;
        const float* Ap = A + (size_t)(row0 + lrow) * K + lk;
        const float* Wp = W + (size_t)(col0 + lrow) * K + lk;
        float acc[8][8];
#pragma unroll
        for (int i = 0; i < 8; i++)
#pragma unroll
            for (int j = 0; j < 8; j++) acc[i][j] = 0.0f;

        for (int k0 = 0; k0 < K; k0 += 8) {
            float4 av = *(const float4*)(Ap + k0);
            float4 wv = *(const float4*)(Wp + k0);
            As[lk + 0][lrow] = av.x; As[lk + 1][lrow] = av.y;
            As[lk + 2][lrow] = av.z; As[lk + 3][lrow] = av.w;
            Ws[lk + 0][lrow] = wv.x; Ws[lk + 1][lrow] = wv.y;
            Ws[lk + 2][lrow] = wv.z; Ws[lk + 3][lrow] = wv.w;
            __syncthreads();
#pragma unroll
            for (int k = 0; k < 8; k++) {
                float a[8], b[8];
                float4 t0 = *(const float4*)(&As[k][ty * 8 + 0]);
                float4 t1 = *(const float4*)(&As[k][ty * 8 + 4]);
                a[0]=t0.x;a[1]=t0.y;a[2]=t0.z;a[3]=t0.w;a[4]=t1.x;a[5]=t1.y;a[6]=t1.z;a[7]=t1.w;
                float4 u0 = *(const float4*)(&Ws[k][tx * 8 + 0]);
                float4 u1 = *(const float4*)(&Ws[k][tx * 8 + 4]);
                b[0]=u0.x;b[1]=u0.y;b[2]=u0.z;b[3]=u0.w;b[4]=u1.x;b[5]=u1.y;b[6]=u1.z;b[7]=u1.w;
#pragma unroll
                for (int i = 0; i < 8; i++)
#pragma unroll
                    for (int j = 0; j < 8; j++) acc[i][j] += a[i] * b[j];
            }
            __syncthreads();
        }
#pragma unroll
        for (int i = 0; i < 8; i++) {
            const size_t r = (size_t)(row0 + ty * 8 + i);
#pragma unroll
            for (int j = 0; j < 8; j++) {
                const int cc = col0 + tx * 8 + j;
                float v = acc[i][j];
                if (bias) v += bias[cc];
                C[r * N + cc] = v;
            }
        }
        __syncthreads();
    }
#endif
}

// =================================================================
// GEMM (256x256 tile) — kv projection, with fused V^T epilogue:
// tiles with n0 >= DIM write ONLY the tf32 transposed V into vtb
// (lane = s is warp-consecutive -> coalesced); K tiles write C.
// =================================================================
#define A256_BYTES 32768
#define STAGE256 (A256_BYTES + B_BYTES)          // 64KB
#define GEMM256_SMEM (2 * STAGE256 + 1024)

__global__ __launch_bounds__(256, 1)
void gemm_tc256(const float* __restrict__ A, const float* __restrict__ W,
                float* __restrict__ C, float* __restrict__ vtb,
                int M, int N, int K)
{
#if HAS_TCGEN05
    extern __shared__ char smraw[];
    __shared__ uint64_t mbar[2];
    __shared__ uint32_t tmem_slot;

    const uint32_t smbase = (smem_u32(smraw) + 1023u) & ~1023u;
    const uint32_t bar0 = smem_u32(&mbar[0]);
    const uint32_t bar1 = smem_u32(&mbar[1]);
    const uint32_t slot = smem_u32(&tmem_slot);

    const int tid = threadIdx.x;
    const int wid = tid >> 5;
    const int lid = tid & 31;
    const int m0 = blockIdx.y * 256;
    const int n0 = blockIdx.x * 256;

    if (wid == 0) TCGEN05_ALLOC(slot, 512);
    if (tid == 0) { MBARRIER_INIT(bar0, 1); MBARRIER_INIT(bar1, 1); }
    __syncthreads();
    uint32_t tmem;
    asm volatile("ld.shared.b32 %0, [%1];" : "=r"(tmem) : "r"(slot));
    if (wid == 0) TCGEN05_RELINQ();

    const uint32_t IDESC = (1u << 4) | (2u << 7) | (2u << 10)
                         | ((256u / 8) << 17) | ((128u / 16) << 24);

    const int NC = K / GK;
    int ph0 = 0, ph1 = 0;

    for (int c = 0; c < NC; c++) {
        const int buf = c & 1;
        const uint32_t barb = buf ? bar1 : bar0;
        if (c >= 2) {
            MBARRIER_WAIT_PARITY(barb, (buf ? ph1 : ph0));
            if (buf) ph1 ^= 1; else ph0 ^= 1;
        }
        const uint32_t sb = smbase + buf * STAGE256;
        const float* Ap = A + (size_t)m0 * K + c * GK;
        const float* Wp = W + (size_t)n0 * K + c * GK;

#pragma unroll
        for (int it = 0; it < 8; it++) {
            int i = tid + it * 256;
            int row = i >> 3, fo = i & 7;
            float4 v = *(const float4*)(Ap + (size_t)row * K + fo * 4);
            uint32_t r0 = f2tf32(v.x), r1 = f2tf32(v.y),
                     r2 = f2tf32(v.z), r3 = f2tf32(v.w);
            uint32_t off = sw128((uint32_t)((row & 127) * 128 + fo * 16));
            uint32_t dst = sb + ((row < 128) ? 0u : 16384u) + off;
            asm volatile("st.shared.v4.b32 [%0], {%1,%2,%3,%4};"
                         :: "r"(dst), "r"(r0), "r"(r1), "r"(r2), "r"(r3) : "memory");
        }
#pragma unroll
        for (int it = 0; it < 8; it++) {
            int i = tid + it * 256;
            int row = i >> 3, fo = i & 7;
            float4 v = *(const float4*)(Wp + (size_t)row * K + fo * 4);
            uint32_t r0 = f2tf32(v.x), r1 = f2tf32(v.y),
                     r2 = f2tf32(v.z), r3 = f2tf32(v.w);
            uint32_t dst = sb + A256_BYTES + sw128((uint32_t)(row * 128 + fo * 16));
            asm volatile("st.shared.v4.b32 [%0], {%1,%2,%3,%4};"
                         :: "r"(dst), "r"(r0), "r"(r1), "r"(r2), "r"(r3) : "memory");
        }
        __syncthreads();

        if (wid == 0 && elect_one()) {
            FENCE_ASYNC();
            const uint64_t dA0 = DESC_BASE | ((uint64_t)(sb >> 4) & 0x3FFF);
            const uint64_t dA1 = DESC_BASE | ((uint64_t)((sb + 16384u) >> 4) & 0x3FFF);
            const uint64_t dB  = DESC_BASE | ((uint64_t)((sb + A256_BYTES) >> 4) & 0x3FFF);
#pragma unroll
            for (int k = 0; k < 4; k++) {
                uint32_t en = (c > 0 || k > 0) ? 1u : 0u;
                mma_tf32_ss(tmem,       dA0 + k * 2, dB + k * 2, IDESC, en);
                mma_tf32_ss(tmem + 256, dA1 + k * 2, dB + k * 2, IDESC, en);
            }
            TCGEN05_COMMIT(barb);
        }
    }

    MBARRIER_WAIT_PARITY(bar0, ph0);
    MBARRIER_WAIT_PARITY(bar1, ph1);
    TCGEN05_FENCE_AFTER();

    {
        const int tile = wid >> 2;
        const uint32_t dbase = tmem + tile * 256;
        const int rowl = (wid & 3) * 32 + lid;
        const size_t grow = (size_t)m0 + tile * 128 + rowl;    // global row = b*SEQ + s

        if (vtb && n0 >= DIM) {
            // V tile: write ONLY transposed tf32 into vtb.
            // vt[((b*NHEADS + h)*HDIM + d) * SEQ + s], h*HDIM+d = n - DIM
            const int s  = (int)(grow & (SEQ - 1));
            const int bq = (int)(grow >> 13);
            const size_t vb0 = (size_t)bq * NHEADS * HDIM;
#pragma unroll
            for (int cb = 0; cb < 8; cb++) {
                uint32_t rr[32];
                TCGEN05_LD_X32(rr, dbase + cb * 32);
                TCGEN05_WAIT_LD();
#pragma unroll
                for (int j = 0; j < 32; j++) {
                    const int dcol = (n0 - DIM) + cb * 32 + j;
                    vtb[(vb0 + (size_t)dcol) * SEQ + s] =
                        __uint_as_float(f2tf32(__uint_as_float(rr[j])));
                }
            }
        } else {
            float* Crow = C + grow * N + n0;
#pragma unroll
            for (int cb = 0; cb < 8; cb++) {
                uint32_t rr[32];
                TCGEN05_LD_X32(rr, dbase + cb * 32);
                TCGEN05_WAIT_LD();
#pragma unroll
                for (int j = 0; j < 32; j += 4) {
                    float4 o;
                    o.x = __uint_as_float(rr[j + 0]);
                    o.y = __uint_as_float(rr[j + 1]);
                    o.z = __uint_as_float(rr[j + 2]);
                    o.w = __uint_as_float(rr[j + 3]);
                    *(float4*)(Crow + cb * 32 + j) = o;
                }
            }
        }
    }
    TCGEN05_FENCE_BEFORE();
    __syncthreads();
    if (wid == 0) TCGEN05_DEALLOC(tmem, 512);

#else
    __shared__ float As[8][128];
    __shared__ float Ws[8][128];
    const int tid  = threadIdx.x;
    const int ty   = tid >> 4;
    const int tx   = tid & 15;
    const int lrow = tid >> 1;
    const int lk   = (tid & 1) * 4;

    for (int hm = 0; hm < 2; hm++)
    for (int hn = 0; hn < 2; hn++) {
        const int row0 = blockIdx.y * 256 + hm * 128;
        const int col0 = blockIdx.x * 256 + hn * 128;
        const float* Ap = A + (size_t)(row0 + lrow) * K + lk;
        const float* Wp = W + (size_t)(col0 + lrow) * K + lk;
        float acc[8][8];
#pragma unroll
        for (int i = 0; i < 8; i++)
#pragma unroll
            for (int j = 0; j < 8; j++) acc[i][j] = 0.0f;

        for (int k0 = 0; k0 < K; k0 += 8) {
            float4 av = *(const float4*)(Ap + k0);
            float4 wv = *(const float4*)(Wp + k0);
            As[lk + 0][lrow] = av.x; As[lk + 1][lrow] = av.y;
            As[lk + 2][lrow] = av.z; As[lk + 3][lrow] = av.w;
            Ws[lk + 0][lrow] = wv.x; Ws[lk + 1][lrow] = wv.y;
            Ws[lk + 2][lrow] = wv.z; Ws[lk + 3][lrow] = wv.w;
            __syncthreads();
#pragma unroll
            for (int k = 0; k < 8; k++) {
                float a[8], b[8];
                float4 t0 = *(const float4*)(&As[k][ty * 8 + 0]);
                float4 t1 = *(const float4*)(&As[k][ty * 8 + 4]);
                a[0]=t0.x;a[1]=t0.y;a[2]=t0.z;a[3]=t0.w;a[4]=t1.x;a[5]=t1.y;a[6]=t1.z;a[7]=t1.w;
                float4 u0 = *(const float4*)(&Ws[k][tx * 8 + 0]);
                float4 u1 = *(const float4*)(&Ws[k][tx * 8 + 4]);
                b[0]=u0.x;b[1]=u0.y;b[2]=u0.z;b[3]=u0.w;b[4]=u1.x;b[5]=u1.y;b[6]=u1.z;b[7]=u1.w;
#pragma unroll
                for (int i = 0; i < 8; i++)
#pragma unroll
                    for (int j = 0; j < 8; j++) acc[i][j] += a[i] * b[j];
            }
            __syncthreads();
        }
#pragma unroll
        for (int i = 0; i < 8; i++) {
            const size_t grow = (size_t)(row0 + ty * 8 + i);
#pragma unroll
            for (int j = 0; j < 8; j++) {
                const int cc = col0 + tx * 8 + j;
                if (vtb && cc >= DIM) {
                    const int s  = (int)(grow & (SEQ - 1));
                    const int bq = (int)(grow >> 13);
                    vtb[((size_t)bq * NHEADS * HDIM + (cc - DIM)) * SEQ + s] =
                        __uint_as_float(f2tf32(acc[i][j]));
                } else {
                    C[grow * N + cc] = acc[i][j];
                }
            }
        }
        __syncthreads();
    }
#endif
}

// =================================================================
// Tensor-core flash attention — round-9 version (proven 251us).
// 2 CTAs/SM (97KB smem, 256 TMEM cols). S->P in-place in TMEM.
// smem: Q 32K | K 32K | VT 32K   TMEM: SP @+0 (128), O @+128 (64)
// =================================================================
#define SCHUNK 128
#define NCH (SEQ / SCHUNK)
#define ATTN_SMEM (3 * 32768 + 1024)
#define SCALE_L2E 0.18033688011112042f   // SCALE * log2(e)

__global__ __launch_bounds__(256, 2)
void attn_tc(const float* __restrict__ q, const float* __restrict__ kv,
             const float* __restrict__ vt, float* __restrict__ out)
{
#if HAS_TCGEN05
    extern __shared__ char smraw[];
    __shared__ uint64_t mbar[2];
    __shared__ uint32_t tmem_slot;
    __shared__ float ls_sh[256];

    const uint32_t smbase = (smem_u32(smraw) + 1023u) & ~1023u;
    const uint32_t QS = smbase;
    const uint32_t KS = smbase + 32768u;
    const uint32_t VS = smbase + 65536u;
    const uint32_t barQK = smem_u32(&mbar[0]);
    const uint32_t barPV = smem_u32(&mbar[1]);
    const uint32_t slot  = smem_u32(&tmem_slot);

    const int tid = threadIdx.x;
    const int wid = tid >> 5;
    const int lid = tid & 31;
    const int bh  = blockIdx.x >> 2;
    const int lt  = blockIdx.x & 3;
    const int b   = bh >> 4, h = bh & 15;
    const int l0  = lt * 128;

    if (wid == 0) TCGEN05_ALLOC(slot, 256);
    if (tid == 0) { MBARRIER_INIT(barQK, 1); MBARRIER_INIT(barPV, 1); }
    __syncthreads();
    uint32_t tmem;
    asm volatile("ld.shared.b32 %0, [%1];" : "=r"(tmem) : "r"(slot));
    if (wid == 0) TCGEN05_RELINQ();
    const uint32_t tmem_SP = tmem;           // S and P share these 128 cols
    const uint32_t tmem_O  = tmem + 128;

    const uint32_t IDESC_S = (1u << 4) | (2u << 7) | (2u << 10)
                           | ((128u / 8) << 17) | ((128u / 16) << 24);
    const uint32_t IDESC_O = (1u << 4) | (2u << 7) | (2u << 10)
                           | ((64u / 8) << 17) | ((128u / 16) << 24);

    const float* kbase = kv + (size_t)b * SEQ * (2 * DIM) + h * HDIM;
    const float* vbase = vt + ((size_t)bh * HDIM) * SEQ;

    // ---- load Q (scaled by SCALE*log2e) ----
    const float* qbase = q + ((size_t)b * LAT + l0) * DIM + h * HDIM;
#pragma unroll
    for (int it = 0; it < 8; it++) {
        int i = tid + it * 256;
        int row = i >> 4, f = i & 15;
        int kc = f >> 3, fo = f & 7;
        float4 v = *(const float4*)(qbase + (size_t)row * DIM + f * 4);
        uint32_t r0 = f2tf32(v.x * SCALE_L2E), r1 = f2tf32(v.y * SCALE_L2E);
        uint32_t r2 = f2tf32(v.z * SCALE_L2E), r3 = f2tf32(v.w * SCALE_L2E);
        uint32_t dst = QS + kc * 16384u + sw128((uint32_t)(row * 128 + fo * 16));
        asm volatile("st.shared.v4.b32 [%0], {%1,%2,%3,%4};"
                     :: "r"(dst), "r"(r0), "r"(r1), "r"(r2), "r"(r3) : "memory");
    }

    auto loadK = [&](int ci) {
        const int s0 = ci * SCHUNK;
#pragma unroll
        for (int it = 0; it < 8; it++) {
            int i = tid + it * 256;
            int kr = i >> 4, f = i & 15;
            int kc = f >> 3, fo = f & 7;
            float4 v = *(const float4*)(kbase + (size_t)(s0 + kr) * (2 * DIM) + f * 4);
            uint32_t r0 = f2tf32(v.x), r1 = f2tf32(v.y),
                     r2 = f2tf32(v.z), r3 = f2tf32(v.w);
            uint32_t dst = KS + kc * 16384u + sw128((uint32_t)(kr * 128 + fo * 16));
            asm volatile("st.shared.v4.b32 [%0], {%1,%2,%3,%4};"
                         :: "r"(dst), "r"(r0), "r"(r1), "r"(r2), "r"(r3) : "memory");
        }
    };
    auto loadVT = [&](int ci) {
        const int s0 = ci * SCHUNK;
#pragma unroll
        for (int it = 0; it < 8; it++) {
            int i = tid + it * 256;
            int d = i >> 5, f = i & 31;
            int sc = f >> 3, fo = f & 7;
            float4 v = *(const float4*)(vbase + (size_t)d * SEQ + s0 + f * 4);
            uint32_t dst = VS + sc * 8192u + sw128((uint32_t)(d * 128 + fo * 16));
            asm volatile("st.shared.v4.b32 [%0], {%1,%2,%3,%4};"
                         :: "r"(dst), "r"(__float_as_uint(v.x)), "r"(__float_as_uint(v.y)),
                            "r"(__float_as_uint(v.z)), "r"(__float_as_uint(v.w)) : "memory");
        }
    };

    const uint64_t dQ0 = DESC_BASE | ((uint64_t)(QS >> 4) & 0x3FFF);
    const uint64_t dQ1 = DESC_BASE | ((uint64_t)((QS + 16384u) >> 4) & 0x3FFF);
    const uint64_t dK0 = DESC_BASE | ((uint64_t)(KS >> 4) & 0x3FFF);
    const uint64_t dK1 = DESC_BASE | ((uint64_t)((KS + 16384u) >> 4) & 0x3FFF);

    float lsum = 0.0f;
    int phQK = 0, phPV = 0;

    loadK(0);
    loadVT(0);
    __syncthreads();

    for (int ci = 0; ci < NCH; ci++) {
        // ---- QK(ci): SP free (PV(ci-1) retired at end of prev iter) ----
        if (wid == 0 && elect_one()) {
            FENCE_ASYNC();
#pragma unroll
            for (int blk = 0; blk < 2; blk++) {
                const uint64_t dq = blk ? dQ1 : dQ0;
                const uint64_t dk = blk ? dK1 : dK0;
#pragma unroll
                for (int ks = 0; ks < 4; ks++)
                    mma_tf32_ss(tmem_SP, dq + ks * 2, dk + ks * 2, IDESC_S,
                                (blk > 0 || ks > 0) ? 1u : 0u);
            }
            TCGEN05_COMMIT(barQK);
        }
        MBARRIER_WAIT_PARITY(barQK, phQK); phQK ^= 1;
        TCGEN05_FENCE_AFTER();

        // ---- softmax in place: warp w -> rows 32*(w&3), cols 64*(w>>2) ----
        {
            const uint32_t colofs = (uint32_t)(wid >> 2) * 64u;
            const uint32_t wlane  = (uint32_t)(wid & 3) << 21;
#pragma unroll
            for (int blk = 0; blk < 2; blk++) {
                uint32_t rr[32];
                TCGEN05_LD_X32(rr, tmem_SP + colofs + blk * 32);
                TCGEN05_WAIT_LD();
#pragma unroll
                for (int j = 0; j < 32; j++) {
                    float p;
                    asm("ex2.approx.f32 %0, %1;" : "=f"(p) : "f"(__uint_as_float(rr[j])));
                    lsum += p;
                    rr[j] = f2tf32(p);
                }
                TCGEN05_ST_X32(tmem_SP + wlane + colofs + blk * 32, rr);
            }
            TCGEN05_WAIT_ST();
        }
        TCGEN05_FENCE_BEFORE();
        __syncthreads();

        // ---- PV(ci): O += P @ VT ----
        if (wid == 0 && elect_one()) {
            TCGEN05_FENCE_AFTER();
            FENCE_ASYNC();
#pragma unroll
            for (int st = 0; st < 16; st++) {
                const uint64_t dV = DESC_BASE
                    | ((uint64_t)((VS + (st >> 2) * 8192u) >> 4) & 0x3FFF);
                mma_tf32_ts(tmem_O, tmem_SP + st * 8, dV + (st & 3) * 2, IDESC_O,
                            (ci > 0 || st > 0) ? 1u : 0u);
            }
            TCGEN05_COMMIT(barPV);
        }

        // ---- loadK(ci+1) under PV shadow (K free: QK(ci) retired) ----
        if (ci + 1 < NCH) loadK(ci + 1);

        // ---- retire PV before overwriting VT / next QK writing SP ----
        MBARRIER_WAIT_PARITY(barPV, phPV); phPV ^= 1;
        if (ci + 1 < NCH) loadVT(ci + 1);
        __syncthreads();
    }

    TCGEN05_FENCE_AFTER();

    // ---- merge column-split lsum partials, then epilogue ----
    ls_sh[tid] = lsum;
    __syncthreads();

    if (wid < 4) {
        const int r = wid * 32 + lid;
        const float inv = 1.0f / (ls_sh[tid] + ls_sh[tid + 128]);
        float* op = out + ((size_t)b * LAT + l0 + r) * DIM + h * HDIM;
#pragma unroll
        for (int cb = 0; cb < 2; cb++) {
            uint32_t rr[32];
            TCGEN05_LD_X32(rr, tmem_O + cb * 32);
            TCGEN05_WAIT_LD();
#pragma unroll
            for (int j = 0; j < 32; j += 4) {
                float4 o;
                o.x = __uint_as_float(rr[j + 0]) * inv;
                o.y = __uint_as_float(rr[j + 1]) * inv;
                o.z = __uint_as_float(rr[j + 2]) * inv;
                o.w = __uint_as_float(rr[j + 3]) * inv;
                *(float4*)(op + cb * 32 + j) = o;
            }
        }
    }
    TCGEN05_FENCE_BEFORE();
    __syncthreads();
    if (wid == 0) TCGEN05_DEALLOC(tmem, 256);

#else
    // SIMT fallback (thread-per-row; never runs on GB300)
    const int tid = threadIdx.x;
    const int bh  = blockIdx.x >> 2;
    const int lt  = blockIdx.x & 3;
    const int b   = bh >> 4, h = bh & 15;
    const int l0  = lt * 128;
    if (tid < 128) {
        const float* qrow = q + ((size_t)b * LAT + l0 + tid) * DIM + h * HDIM;
        const float* kb = kv + (size_t)b * SEQ * (2 * DIM) + h * HDIM;
        const float* vb = vt + ((size_t)bh * HDIM) * SEQ;
        float qr[64];
#pragma unroll
        for (int d = 0; d < 64; d++) qr[d] = qrow[d] * SCALE;
        float O[64];
#pragma unroll
        for (int d = 0; d < 64; d++) O[d] = 0.0f;
        float l = 0.0f;
        for (int s = 0; s < SEQ; s++) {
            const float* kr = kb + (size_t)s * (2 * DIM);
            float sv = 0.0f;
#pragma unroll 16
            for (int d = 0; d < 64; d++) sv += qr[d] * kr[d];
            float p = __expf(sv);
            l += p;
#pragma unroll 16
            for (int d = 0; d < 64; d++) O[d] += p * vb[(size_t)d * SEQ + s];
        }
        float* op = out + ((size_t)b * LAT + l0 + tid) * DIM + h * HDIM;
        float inv = 1.0f / l;
#pragma unroll
        for (int d = 0; d < 64; d++) op[d] = O[d] * inv;
    }
#endif
}

// =================================================================
// launch
// =================================================================
extern "C" void kernel_launch(void* const* d_in, const int* in_sizes, int n_in,
                              void* d_out, int out_size)
{
    const float* x       = (const float*)d_in[0];
    const float* latents = (const float*)d_in[1];
    if (in_sizes[0] != BATCH * SEQ * DIM) {
        x       = (const float*)d_in[1];
        latents = (const float*)d_in[0];
    }
    const float* w_q   = (const float*)d_in[2];
    const float* w_kv  = (const float*)d_in[3];
    const float* w_out = (const float*)d_in[4];
    const float* b_out = (const float*)d_in[5];
    float* out = (float*)d_out;

    float *q, *kvbuf, *att, *vt;
    cudaGetSymbolAddress((void**)&q,     g_q);
    cudaGetSymbolAddress((void**)&kvbuf, g_kv);
    cudaGetSymbolAddress((void**)&att,   g_att);
    cudaGetSymbolAddress((void**)&vt,    g_vt);

    const int M_q  = BATCH * LAT;    // 2048
    const int M_kv = BATCH * SEQ;    // 32768

    cudaFuncSetAttribute(gemm_tc,    cudaFuncAttributeMaxDynamicSharedMemorySize, GEMM_SMEM);
    cudaFuncSetAttribute(gemm_tc256, cudaFuncAttributeMaxDynamicSharedMemorySize, GEMM256_SMEM);
    cudaFuncSetAttribute(attn_tc,    cudaFuncAttributeMaxDynamicSharedMemorySize, ATTN_SMEM);

    // 1) q = latents @ w_q^T        (2048 x 1024)
    gemm_tc<<<dim3(DIM / 256, M_q / 128), 256, GEMM_SMEM>>>(latents, w_q, q, nullptr,
                                                            M_q, DIM, DIM);
    // 2) kv = x @ w_kv^T            (32768 x 2048) — V half goes straight to vt (tf32, transposed)
    gemm_tc256<<<dim3(2 * DIM / 256, M_kv / 256), 256, GEMM256_SMEM>>>(
        x, w_kv, kvbuf, vt, M_kv, 2 * DIM, DIM);
    // 3) attention (vt produced by the fused epilogue above)
    attn_tc<<<BATCH * NHEADS * (LAT / 128), 256, ATTN_SMEM>>>(q, kvbuf, vt, att);
    // 4) out = att @ w_out^T + b_out
    gemm_tc<<<dim3(DIM / 256, M_q / 128), 256, GEMM_SMEM>>>(att, w_out, out, b_out,
                                                            M_q, DIM, DIM);
}